// round 2
// baseline (speedup 1.0000x reference)
#include <cuda_runtime.h>
#include <float.h>

// ---------------------------------------------------------------------------
// GAT 2-layer forward for GB300.
// Pipeline: CSR build (zero, hist, scan, scatter) -> SGEMM1 -> attn1 ->
//           agg1(+bias+ELU) -> SGEMM2 -> attn2 -> agg2(+bias) -> d_out.
// All scratch in __device__ globals (no allocation, graph-capturable).
// edge_index is int32 (JAX default x64-disabled downgrades int64 -> int32).
// ---------------------------------------------------------------------------

#define NMAX 50048
#define EMAX 800000
#define EPMAX (EMAX + NMAX)

__device__ int   g_deg[NMAX];
__device__ int   g_wp[NMAX];
__device__ int   g_rowptr[NMAX + 1];
__device__ int   g_col[EPMAX];
__device__ float g_h1  [(size_t)NMAX * 128];
__device__ float g_out1[(size_t)NMAX * 128];
__device__ float g_h2  [(size_t)NMAX * 64];
__device__ float g_as1[NMAX * 4];
__device__ float g_ad1[NMAX * 4];
__device__ float g_as2[NMAX];
__device__ float g_ad2[NMAX];

// ---------------------------------------------------------------------------
// CSR construction
// ---------------------------------------------------------------------------

__global__ void zero_deg_kernel(int N) {
    int i = blockIdx.x * blockDim.x + threadIdx.x;
    if (i < N) g_deg[i] = 0;
}

__global__ void hist_kernel(const int* __restrict__ ei, int E, int N) {
    int i = blockIdx.x * blockDim.x + threadIdx.x;
    int EP = E + N;
    if (i >= EP) return;
    int d = (i < E) ? ei[E + i] : (i - E);   // self-loops appended
    atomicAdd(&g_deg[d], 1);
}

// Single-block exclusive scan of g_deg into g_rowptr (and g_wp copy).
__global__ void scan_kernel(int N) {
    __shared__ int sums[1024];
    int t = threadIdx.x;
    int chunk = (N + 1023) / 1024;
    int c0 = t * chunk;
    int c1 = min(c0 + chunk, N);
    int s = 0;
    for (int i = c0; i < c1; i++) s += g_deg[i];
    sums[t] = s;
    __syncthreads();
    for (int off = 1; off < 1024; off <<= 1) {
        int v = (t >= off) ? sums[t - off] : 0;
        __syncthreads();
        sums[t] += v;
        __syncthreads();
    }
    int run = sums[t] - s;  // exclusive prefix for this thread's chunk
    for (int i = c0; i < c1; i++) {
        g_rowptr[i] = run;
        g_wp[i]     = run;
        run += g_deg[i];
    }
    if (t == 1023) g_rowptr[N] = sums[1023];
}

__global__ void scatter_kernel(const int* __restrict__ ei, int E, int N) {
    int i = blockIdx.x * blockDim.x + threadIdx.x;
    int EP = E + N;
    if (i >= EP) return;
    int s, d;
    if (i < E) { s = ei[i]; d = ei[E + i]; }
    else       { s = d = i - E; }
    int p = atomicAdd(&g_wp[d], 1);
    g_col[p] = s;
}

// ---------------------------------------------------------------------------
// SGEMM: C[M x NCOLS] = A[M x 128] @ W[128 x NCOLS]  (row-major, fp32)
// Tile: 64 rows x NCOLS cols per 256-thread block, K chunked by 64.
// ---------------------------------------------------------------------------

template <int NCOLS>
__global__ __launch_bounds__(256)
void sgemm_kernel(const float* __restrict__ A, const float* __restrict__ W,
                  float* __restrict__ C, int M) {
    constexpr int KD = 128, KC = 64, MT = 64;
    constexpr int CG  = NCOLS / 4;              // col-groups (float4 each)
    constexpr int RPT = (MT * CG) / 256;        // rows per thread
    __shared__ float As[MT][KC];
    __shared__ float Ws[KC][NCOLS];

    int tid = threadIdx.x;
    int cg  = tid % CG;
    int rg  = tid / CG;
    int row0 = blockIdx.x * MT;

    float acc[RPT][4];
#pragma unroll
    for (int r = 0; r < RPT; r++)
#pragma unroll
        for (int q = 0; q < 4; q++) acc[r][q] = 0.f;

    for (int kc = 0; kc < KD; kc += KC) {
        for (int i = tid; i < MT * KC / 4; i += 256) {
            int r  = i / (KC / 4);
            int c4 = i % (KC / 4);
            float4 v = make_float4(0.f, 0.f, 0.f, 0.f);
            if (row0 + r < M)
                v = *(const float4*)&A[(size_t)(row0 + r) * KD + kc + c4 * 4];
            *(float4*)&As[r][c4 * 4] = v;
        }
        for (int i = tid; i < KC * NCOLS / 4; i += 256) {
            int r  = i / (NCOLS / 4);
            int c4 = i % (NCOLS / 4);
            *(float4*)&Ws[r][c4 * 4] = *(const float4*)&W[(size_t)(kc + r) * NCOLS + c4 * 4];
        }
        __syncthreads();
#pragma unroll 8
        for (int k = 0; k < KC; k++) {
            float4 w = *(float4*)&Ws[k][cg * 4];
#pragma unroll
            for (int r = 0; r < RPT; r++) {
                float xv = As[rg * RPT + r][k];
                acc[r][0] = fmaf(xv, w.x, acc[r][0]);
                acc[r][1] = fmaf(xv, w.y, acc[r][1]);
                acc[r][2] = fmaf(xv, w.z, acc[r][2]);
                acc[r][3] = fmaf(xv, w.w, acc[r][3]);
            }
        }
        __syncthreads();
    }
#pragma unroll
    for (int r = 0; r < RPT; r++) {
        int row = row0 + rg * RPT + r;
        if (row < M) {
            float4 v = make_float4(acc[r][0], acc[r][1], acc[r][2], acc[r][3]);
            *(float4*)&C[(size_t)row * NCOLS + cg * 4] = v;
        }
    }
}

// ---------------------------------------------------------------------------
// Attention coefficients: a_s[n][h] = <h[n,h,:], att_src[h,:]>, same for a_d.
// One warp per node; lane-parallel over channels, butterfly reduce per head.
// ---------------------------------------------------------------------------

template <int H, int C>
__global__ void attn_kernel(const float* __restrict__ hin,
                            const float* __restrict__ ws, const float* __restrict__ wd,
                            float* __restrict__ a_s, float* __restrict__ a_d, int N) {
    int gw   = (blockIdx.x * blockDim.x + threadIdx.x) >> 5;
    int lane = threadIdx.x & 31;
    if (gw >= N) return;
    const float* hr = hin + (size_t)gw * (H * C);
    float ps[H], pd[H];
#pragma unroll
    for (int h = 0; h < H; h++) { ps[h] = 0.f; pd[h] = 0.f; }
#pragma unroll
    for (int h = 0; h < H; h++)
        for (int c = lane; c < C; c += 32) {
            float v = hr[h * C + c];
            ps[h] += v * __ldg(&ws[h * C + c]);
            pd[h] += v * __ldg(&wd[h * C + c]);
        }
#pragma unroll
    for (int h = 0; h < H; h++)
        for (int off = 16; off > 0; off >>= 1) {
            ps[h] += __shfl_xor_sync(0xffffffffu, ps[h], off);
            pd[h] += __shfl_xor_sync(0xffffffffu, pd[h], off);
        }
    if (lane == 0) {
#pragma unroll
        for (int h = 0; h < H; h++) {
            a_s[gw * H + h] = ps[h];
            a_d[gw * H + h] = pd[h];
        }
    }
}

// ---------------------------------------------------------------------------
// Per-destination segment softmax + weighted aggregation. One warp per node.
// Pass1: max(e), Pass2: sum(exp), Pass3: gather h[src] * alpha (SHFL bcast).
// ---------------------------------------------------------------------------

template <int H, int C, bool ELU_OUT>
__global__ void agg_kernel(const float* __restrict__ hin,
                           const float* __restrict__ a_s, const float* __restrict__ a_dv,
                           const float* __restrict__ bias,
                           float* __restrict__ out, int N) {
    constexpr int F  = H * C;
    constexpr int NC = C / 32;
    int gw   = (blockIdx.x * blockDim.x + threadIdx.x) >> 5;
    int lane = threadIdx.x & 31;
    if (gw >= N) return;
    int n = gw;

    float ad[H];
#pragma unroll
    for (int h = 0; h < H; h++) ad[h] = __ldg(&a_dv[n * H + h]);
    int beg = g_rowptr[n], end = g_rowptr[n + 1];

    // pass 1: per-head max of leaky_relu(a_s[src] + a_d[dst])
    float m[H];
#pragma unroll
    for (int h = 0; h < H; h++) m[h] = -FLT_MAX;
    for (int i = beg + lane; i < end; i += 32) {
        int s = g_col[i];
#pragma unroll
        for (int h = 0; h < H; h++) {
            float e = __ldg(&a_s[s * H + h]) + ad[h];
            e = (e > 0.f) ? e : 0.2f * e;
            m[h] = fmaxf(m[h], e);
        }
    }
#pragma unroll
    for (int h = 0; h < H; h++)
        for (int off = 16; off > 0; off >>= 1)
            m[h] = fmaxf(m[h], __shfl_xor_sync(0xffffffffu, m[h], off));

    // pass 2: sum of exp(e - max)
    float inv[H];
#pragma unroll
    for (int h = 0; h < H; h++) inv[h] = 0.f;
    for (int i = beg + lane; i < end; i += 32) {
        int s = g_col[i];
#pragma unroll
        for (int h = 0; h < H; h++) {
            float e = __ldg(&a_s[s * H + h]) + ad[h];
            e = (e > 0.f) ? e : 0.2f * e;
            inv[h] += __expf(e - m[h]);
        }
    }
#pragma unroll
    for (int h = 0; h < H; h++) {
        for (int off = 16; off > 0; off >>= 1)
            inv[h] += __shfl_xor_sync(0xffffffffu, inv[h], off);
        inv[h] = 1.f / inv[h];   // self-loop guarantees > 0
    }

    // pass 3: acc[h][c] = sum_e alpha_e * h[src_e][h*C + c*32 + lane]
    float acc[H][NC];
#pragma unroll
    for (int h = 0; h < H; h++)
#pragma unroll
        for (int c = 0; c < NC; c++) acc[h][c] = 0.f;

    for (int base = beg; base < end; base += 32) {
        int idx = base + lane;
        bool valid = idx < end;
        int sl = valid ? g_col[idx] : 0;
        float av[H];
#pragma unroll
        for (int h = 0; h < H; h++) {
            float e = valid ? (__ldg(&a_s[sl * H + h]) + ad[h]) : 0.f;
            e = (e > 0.f) ? e : 0.2f * e;
            av[h] = valid ? __expf(e - m[h]) * inv[h] : 0.f;
        }
        int cnt = min(32, end - base);
        for (int j = 0; j < cnt; j++) {
            int s = __shfl_sync(0xffffffffu, sl, j);
            const float* hr = hin + (size_t)s * F;
#pragma unroll
            for (int h = 0; h < H; h++) {
                float a = __shfl_sync(0xffffffffu, av[h], j);
#pragma unroll
                for (int c = 0; c < NC; c++)
                    acc[h][c] = fmaf(__ldg(&hr[h * C + c * 32 + lane]), a, acc[h][c]);
            }
        }
    }

    // epilogue: + bias, optional ELU
#pragma unroll
    for (int h = 0; h < H; h++)
#pragma unroll
        for (int c = 0; c < NC; c++) {
            int f = h * C + c * 32 + lane;
            float v = acc[h][c] + __ldg(&bias[f]);
            if (ELU_OUT) v = (v > 0.f) ? v : (__expf(v) - 1.f);
            out[(size_t)n * F + f] = v;
        }
}

// ---------------------------------------------------------------------------
// Launch
// ---------------------------------------------------------------------------

extern "C" void kernel_launch(void* const* d_in, const int* in_sizes, int n_in,
                              void* d_out, int out_size) {
    const float* x    = (const float*)d_in[0];
    const int*   ei   = (const int*)d_in[1];   // int32 [2, E] (JAX x64 disabled)
    const float* W1   = (const float*)d_in[2];
    const float* as1w = (const float*)d_in[3];
    const float* ad1w = (const float*)d_in[4];
    const float* b1   = (const float*)d_in[5];
    const float* W2   = (const float*)d_in[6];
    const float* as2w = (const float*)d_in[7];
    const float* ad2w = (const float*)d_in[8];
    const float* b2   = (const float*)d_in[9];
    float* out = (float*)d_out;

    int N  = in_sizes[0] / 128;
    int E  = in_sizes[1] / 2;
    int EP = E + N;

    void *p_h1, *p_out1, *p_h2, *p_as1, *p_ad1, *p_as2, *p_ad2;
    cudaGetSymbolAddress(&p_h1,   g_h1);
    cudaGetSymbolAddress(&p_out1, g_out1);
    cudaGetSymbolAddress(&p_h2,   g_h2);
    cudaGetSymbolAddress(&p_as1,  g_as1);
    cudaGetSymbolAddress(&p_ad1,  g_ad1);
    cudaGetSymbolAddress(&p_as2,  g_as2);
    cudaGetSymbolAddress(&p_ad2,  g_ad2);

    int nodeBlocks = (N + 255) / 256;
    int edgeBlocks = (EP + 255) / 256;
    int warpBlocks = (N + 7) / 8;          // 8 warps / 256-thread block
    int gemmBlocks = (N + 63) / 64;

    // CSR build (recomputed every launch — no caching allowed)
    zero_deg_kernel<<<nodeBlocks, 256>>>(N);
    hist_kernel<<<edgeBlocks, 256>>>(ei, E, N);
    scan_kernel<<<1, 1024>>>(N);
    scatter_kernel<<<edgeBlocks, 256>>>(ei, E, N);

    // Layer 1: h1 = x @ W1; attention; softmax-aggregate; +b1; ELU
    sgemm_kernel<128><<<gemmBlocks, 256>>>(x, W1, (float*)p_h1, N);
    attn_kernel<4, 32><<<warpBlocks, 256>>>((const float*)p_h1, as1w, ad1w,
                                            (float*)p_as1, (float*)p_ad1, N);
    agg_kernel<4, 32, true><<<warpBlocks, 256>>>((const float*)p_h1,
                                                 (const float*)p_as1, (const float*)p_ad1,
                                                 b1, (float*)p_out1, N);

    // Layer 2: h2 = elu_out @ W2; attention; softmax-aggregate; +b2 -> d_out
    sgemm_kernel<64><<<gemmBlocks, 256>>>((const float*)p_out1, W2, (float*)p_h2, N);
    attn_kernel<1, 64><<<warpBlocks, 256>>>((const float*)p_h2, as2w, ad2w,
                                            (float*)p_as2, (float*)p_ad2, N);
    agg_kernel<1, 64, false><<<warpBlocks, 256>>>((const float*)p_h2,
                                                  (const float*)p_as2, (const float*)p_ad2,
                                                  b2, out, N);
}

// round 3
// speedup vs baseline: 1.5496x; 1.5496x over previous
#include <cuda_runtime.h>
#include <float.h>

// ---------------------------------------------------------------------------
// GAT 2-layer forward, GB300 (sm_103a).
// R3: f32x2 packed-FMA SGEMM with fused attention epilogue + global-shift
//     single-pass softmax aggregation + vectorized CSR build.
// Launches: zero, hist, scan, scatter, sgemm1, agg1, sgemm2, agg2.
// ---------------------------------------------------------------------------

#define NMAX 50048
#define EMAX 800000
#define EPMAX (EMAX + NMAX)

__device__ int      g_deg[NMAX];
__device__ int      g_wp[NMAX];
__device__ int      g_rowptr[NMAX + 1];
__device__ int      g_col[EPMAX];
__device__ float    g_h1  [(size_t)NMAX * 128];
__device__ float    g_out1[(size_t)NMAX * 128];
__device__ float    g_h2  [(size_t)NMAX * 64];
__device__ float    g_as1[NMAX * 4];
__device__ float    g_ad1[NMAX * 4];
__device__ float    g_as2[NMAX];
__device__ float    g_ad2[NMAX];
__device__ unsigned g_Mu[8];   // [0..3]: layer-1 per-head max(a_s), [4]: layer-2

// ---- helpers ---------------------------------------------------------------

typedef unsigned long long u64;

__device__ __forceinline__ u64 pack2(float lo, float hi) {
    u64 r; asm("mov.b64 %0, {%1, %2};" : "=l"(r) : "f"(lo), "f"(hi)); return r;
}
__device__ __forceinline__ u64 fma2(u64 a, u64 b, u64 c) {
    u64 d; asm("fma.rn.f32x2 %0, %1, %2, %3;" : "=l"(d) : "l"(a), "l"(b), "l"(c)); return d;
}
__device__ __forceinline__ float2 unpack2(u64 v) {
    float lo, hi; asm("mov.b64 {%0, %1}, %2;" : "=f"(lo), "=f"(hi) : "l"(v));
    return make_float2(lo, hi);
}
// order-preserving float<->uint encoding for atomicMax on floats
__device__ __forceinline__ unsigned encf(float f) {
    unsigned b = __float_as_uint(f);
    return (b & 0x80000000u) ? ~b : (b | 0x80000000u);
}
__device__ __forceinline__ float decf(unsigned u) {
    return __uint_as_float((u & 0x80000000u) ? (u ^ 0x80000000u) : ~u);
}

// ---------------------------------------------------------------------------
// CSR construction
// ---------------------------------------------------------------------------

__global__ void zero_kernel(int N) {
    int i = blockIdx.x * blockDim.x + threadIdx.x;
    if (i < N) g_deg[i] = 1;          // self loop pre-counted
    if (i < 8) g_Mu[i] = 0u;          // enc(-inf) < enc(any finite float)
}

__global__ void hist_kernel(const int* __restrict__ ei, int E) {
    int i = blockIdx.x * blockDim.x + threadIdx.x;
    int base = i * 4;
    if (base >= E) return;
    if (base + 3 < E) {
        int4 d4 = *(const int4*)&ei[E + base];
        atomicAdd(&g_deg[d4.x], 1);
        atomicAdd(&g_deg[d4.y], 1);
        atomicAdd(&g_deg[d4.z], 1);
        atomicAdd(&g_deg[d4.w], 1);
    } else {
        for (int k = base; k < E; k++) atomicAdd(&g_deg[ei[E + k]], 1);
    }
}

// single block, smem-staged exclusive scan of g_deg -> g_rowptr (+g_wp)
__global__ void scan_kernel(int N) {
    extern __shared__ int sm[];
    int* sdeg = sm;                 // [N]
    int* ssum = sm + N;             // [1024] inclusive chunk sums
    int* soff = sm + N + 1024;      // [1024] exclusive chunk offsets
    int t = threadIdx.x;
    int chunk = (N + 1023) / 1024;

    for (int i = t; i < N; i += 1024) sdeg[i] = g_deg[i];
    __syncthreads();

    int c0 = t * chunk;
    int c1 = min(c0 + chunk, N);
    int run = 0;
    for (int i = c0; i < c1; i++) { int v = sdeg[i]; sdeg[i] = run; run += v; }
    ssum[t] = run;
    __syncthreads();
    for (int off = 1; off < 1024; off <<= 1) {
        int v = (t >= off) ? ssum[t - off] : 0;
        __syncthreads();
        ssum[t] += v;
        __syncthreads();
    }
    soff[t] = ssum[t] - run;
    __syncthreads();

    for (int i = t; i < N; i += 1024) {
        int rp = sdeg[i] + soff[i / chunk];
        g_rowptr[i] = rp;
        g_wp[i]     = rp;
    }
    if (t == 1023) g_rowptr[N] = ssum[1023];
}

__global__ void scatter_kernel(const int* __restrict__ ei, int E, int N) {
    int EV = (E + 3) / 4;
    int i = blockIdx.x * blockDim.x + threadIdx.x;
    if (i < EV) {
        int base = i * 4;
        if (base + 3 < E) {
            int4 s4 = *(const int4*)&ei[base];
            int4 d4 = *(const int4*)&ei[E + base];
            int p0 = atomicAdd(&g_wp[d4.x], 1);
            int p1 = atomicAdd(&g_wp[d4.y], 1);
            int p2 = atomicAdd(&g_wp[d4.z], 1);
            int p3 = atomicAdd(&g_wp[d4.w], 1);
            g_col[p0] = s4.x; g_col[p1] = s4.y; g_col[p2] = s4.z; g_col[p3] = s4.w;
        } else {
            for (int k = base; k < E; k++) {
                int p = atomicAdd(&g_wp[ei[E + k]], 1);
                g_col[p] = ei[k];
            }
        }
    } else if (i - EV < N) {
        int node = i - EV;
        int p = atomicAdd(&g_wp[node], 1);
        g_col[p] = node;
    }
}

// ---------------------------------------------------------------------------
// SGEMM + fused attention epilogue.
// C[M x NCOLS] = A[M x 128] @ W[128 x NCOLS]; also
//   a_s[n,h] = <C[n, h*Ch : (h+1)*Ch], att_s[h]>, same for a_d,
//   g_Mu[mu0+h] = encoded global max of a_s.
// Tile: 64 rows x NCOLS per 256-thread block; K chunked by 32; f32x2 FMA.
// ---------------------------------------------------------------------------

template <int NCOLS, int H>
__global__ __launch_bounds__(256)
void sgemm_attn_kernel(const float* __restrict__ A, const float* __restrict__ W,
                       float* __restrict__ C, const float* __restrict__ att_s,
                       const float* __restrict__ att_d,
                       float* __restrict__ a_s, float* __restrict__ a_d,
                       int mu0, int M) {
    constexpr int KD = 128, KC = 32, MT = 64;
    constexpr int CG  = NCOLS / 4;           // lanes spanning the column dim
    constexpr int RPT = MT * CG / 256;       // rows per thread (8 or 4)
    constexpr int CH  = NCOLS / H;           // channels per head
    constexpr int LPG = CH / 4;              // lanes per head group

    __shared__ float As[KC][MT + 4];         // transposed A tile, padded
    __shared__ float Ws[KC][NCOLS];
    __shared__ unsigned sm_mx[H];

    int tid = threadIdx.x;
    int cg  = tid % CG;
    int rg  = tid / CG;
    int row0 = blockIdx.x * MT;
    if (tid < H) sm_mx[tid] = 0u;

    u64 acc[RPT][2];
#pragma unroll
    for (int r = 0; r < RPT; r++) { acc[r][0] = 0ull; acc[r][1] = 0ull; }

    for (int kc = 0; kc < KD; kc += KC) {
        // load A tile transposed: As[k][row]
        for (int i = tid; i < MT * KC / 4; i += 256) {
            int r  = i / (KC / 4);
            int c4 = i % (KC / 4);
            float4 v = make_float4(0.f, 0.f, 0.f, 0.f);
            if (row0 + r < M)
                v = *(const float4*)&A[(size_t)(row0 + r) * KD + kc + c4 * 4];
            As[c4 * 4 + 0][r] = v.x;
            As[c4 * 4 + 1][r] = v.y;
            As[c4 * 4 + 2][r] = v.z;
            As[c4 * 4 + 3][r] = v.w;
        }
        // load W tile
        for (int i = tid; i < KC * NCOLS / 4; i += 256) {
            int r  = i / (NCOLS / 4);
            int c4 = i % (NCOLS / 4);
            *(float4*)&Ws[r][c4 * 4] = *(const float4*)&W[(size_t)(kc + r) * NCOLS + c4 * 4];
        }
        __syncthreads();
#pragma unroll 8
        for (int k = 0; k < KC; k++) {
            const u64* wp = reinterpret_cast<const u64*>(&Ws[k][cg * 4]);
            u64 w01 = wp[0], w23 = wp[1];
            float av[RPT];
#pragma unroll
            for (int p = 0; p < RPT / 4; p++) {
                float4 a4 = *(const float4*)&As[k][rg * RPT + p * 4];
                av[p * 4 + 0] = a4.x; av[p * 4 + 1] = a4.y;
                av[p * 4 + 2] = a4.z; av[p * 4 + 3] = a4.w;
            }
#pragma unroll
            for (int r = 0; r < RPT; r++) {
                u64 xx = pack2(av[r], av[r]);
                acc[r][0] = fma2(xx, w01, acc[r][0]);
                acc[r][1] = fma2(xx, w23, acc[r][1]);
            }
        }
        __syncthreads();
    }

    // epilogue: store C, fused attention dot-products, block/global max
    int col = cg * 4;
    float w_s0 = __ldg(&att_s[col]),     w_s1 = __ldg(&att_s[col + 1]);
    float w_s2 = __ldg(&att_s[col + 2]), w_s3 = __ldg(&att_s[col + 3]);
    float w_d0 = __ldg(&att_d[col]),     w_d1 = __ldg(&att_d[col + 1]);
    float w_d2 = __ldg(&att_d[col + 2]), w_d3 = __ldg(&att_d[col + 3]);

#pragma unroll
    for (int r = 0; r < RPT; r++) {
        int row = row0 + rg * RPT + r;
        float2 c01 = unpack2(acc[r][0]);
        float2 c23 = unpack2(acc[r][1]);
        if (row < M)
            *(float4*)&C[(size_t)row * NCOLS + col] =
                make_float4(c01.x, c01.y, c23.x, c23.y);
        float ps = c01.x * w_s0 + c01.y * w_s1 + c23.x * w_s2 + c23.y * w_s3;
        float pd = c01.x * w_d0 + c01.y * w_d1 + c23.x * w_d2 + c23.y * w_d3;
#pragma unroll
        for (int off = LPG / 2; off > 0; off >>= 1) {
            ps += __shfl_xor_sync(0xffffffffu, ps, off);
            pd += __shfl_xor_sync(0xffffffffu, pd, off);
        }
        if ((cg % LPG) == 0 && row < M) {
            int h = cg / LPG;
            a_s[row * H + h] = ps;
            a_d[row * H + h] = pd;
            atomicMax(&sm_mx[h], encf(ps));
        }
    }
    __syncthreads();
    if (tid < H) atomicMax(&g_Mu[mu0 + tid], sm_mx[tid]);
}

// ---------------------------------------------------------------------------
// Single-pass softmax aggregation. One warp per destination node.
// Global-shift softmax: S = leaky(max_global(a_s) + a_d[n,h]) >= true max.
// Each lane owns VEC consecutive channels; denominator accumulates
// redundantly per lane (identical within a head group) -> no reduction.
// ---------------------------------------------------------------------------

template <int H, int C, int VEC, bool ELU_OUT>
__global__ void agg_kernel(const float* __restrict__ hin,
                           const float* __restrict__ a_s,
                           const float* __restrict__ a_dv,
                           const float* __restrict__ bias,
                           float* __restrict__ out, int mu0, int N) {
    constexpr int F = H * C;
    int gw   = (blockIdx.x * blockDim.x + threadIdx.x) >> 5;
    int lane = threadIdx.x & 31;
    if (gw >= N) return;

    int   h_own = (lane * VEC) / C;
    float ad    = __ldg(&a_dv[gw * H + h_own]);
    float tM    = decf(g_Mu[mu0 + h_own]) + ad;
    float S     = fmaxf(tM, 0.2f * tM);

    int beg = g_rowptr[gw], end = g_rowptr[gw + 1];
    float d = 0.f;
    float acc[VEC];
#pragma unroll
    for (int q = 0; q < VEC; q++) acc[q] = 0.f;

    for (int base = beg; base < end; base += 32) {
        int idx = base + lane;
        int sl  = (idx < end) ? g_col[idx] : 0;
        int cnt = min(32, end - base);
#pragma unroll 4
        for (int j = 0; j < cnt; j++) {
            int s = __shfl_sync(0xffffffffu, sl, j);
            float e = __ldg(&a_s[s * H + h_own]) + ad;
            e = fmaxf(e, 0.2f * e);
            float ev = __expf(e - S);
            d += ev;
            const float* hr = hin + (size_t)s * F + lane * VEC;
            if (VEC == 4) {
                float4 hv = __ldg((const float4*)hr);
                acc[0] = fmaf(ev, hv.x, acc[0]);
                acc[1] = fmaf(ev, hv.y, acc[1]);
                acc[2] = fmaf(ev, hv.z, acc[2]);
                acc[3] = fmaf(ev, hv.w, acc[3]);
            } else {
                float2 hv = __ldg((const float2*)hr);
                acc[0] = fmaf(ev, hv.x, acc[0]);
                acc[1] = fmaf(ev, hv.y, acc[1]);
            }
        }
    }

    float inv = 1.f / d;
#pragma unroll
    for (int q = 0; q < VEC; q++) {
        int f = lane * VEC + q;
        float v = acc[q] * inv + __ldg(&bias[f]);
        if (ELU_OUT) v = (v > 0.f) ? v : (__expf(v) - 1.f);
        out[(size_t)gw * F + f] = v;
    }
}

// ---------------------------------------------------------------------------
// Launch
// ---------------------------------------------------------------------------

extern "C" void kernel_launch(void* const* d_in, const int* in_sizes, int n_in,
                              void* d_out, int out_size) {
    const float* x    = (const float*)d_in[0];
    const int*   ei   = (const int*)d_in[1];   // int32 [2, E]
    const float* W1   = (const float*)d_in[2];
    const float* as1w = (const float*)d_in[3];
    const float* ad1w = (const float*)d_in[4];
    const float* b1   = (const float*)d_in[5];
    const float* W2   = (const float*)d_in[6];
    const float* as2w = (const float*)d_in[7];
    const float* ad2w = (const float*)d_in[8];
    const float* b2   = (const float*)d_in[9];
    float* out = (float*)d_out;

    int N  = in_sizes[0] / 128;
    int E  = in_sizes[1] / 2;

    void *p_h1, *p_out1, *p_h2, *p_as1, *p_ad1, *p_as2, *p_ad2;
    cudaGetSymbolAddress(&p_h1,   g_h1);
    cudaGetSymbolAddress(&p_out1, g_out1);
    cudaGetSymbolAddress(&p_h2,   g_h2);
    cudaGetSymbolAddress(&p_as1,  g_as1);
    cudaGetSymbolAddress(&p_ad1,  g_ad1);
    cudaGetSymbolAddress(&p_as2,  g_as2);
    cudaGetSymbolAddress(&p_ad2,  g_ad2);

    int scanSmem = (N + 2048) * (int)sizeof(int);
    cudaFuncSetAttribute(scan_kernel, cudaFuncAttributeMaxDynamicSharedMemorySize, scanSmem);

    int nodeBlocks  = (N + 255) / 256;
    int histBlocks  = ((E + 3) / 4 + 255) / 256;
    int scatBlocks  = ((E + 3) / 4 + N + 255) / 256;
    int warpBlocks  = (N + 7) / 8;
    int gemmBlocks  = (N + 63) / 64;

    // CSR build
    zero_kernel<<<nodeBlocks, 256>>>(N);
    hist_kernel<<<histBlocks, 256>>>(ei, E);
    scan_kernel<<<1, 1024, scanSmem>>>(N);
    scatter_kernel<<<scatBlocks, 256>>>(ei, E, N);

    // Layer 1
    sgemm_attn_kernel<128, 4><<<gemmBlocks, 256>>>(
        x, W1, (float*)p_h1, as1w, ad1w, (float*)p_as1, (float*)p_ad1, 0, N);
    agg_kernel<4, 32, 4, true><<<warpBlocks, 256>>>(
        (const float*)p_h1, (const float*)p_as1, (const float*)p_ad1,
        b1, (float*)p_out1, 0, N);

    // Layer 2
    sgemm_attn_kernel<64, 1><<<gemmBlocks, 256>>>(
        (const float*)p_out1, W2, (float*)p_h2, as2w, ad2w,
        (float*)p_as2, (float*)p_ad2, 4, N);
    agg_kernel<1, 64, 2, false><<<warpBlocks, 256>>>(
        (const float*)p_h2, (const float*)p_as2, (const float*)p_ad2,
        b2, out, 4, N);
}